// round 3
// baseline (speedup 1.0000x reference)
#include <cuda_runtime.h>

// Problem constants
#define INSZ   128
#define OUTSZ  128
#define HID    8
#define BATCH  1024
#define NSUB   (INSZ * OUTSZ)

#define NCHUNK 16
#define BC     (BATCH / NCHUNK)   // 64 batch elems per block
#define NF     97                 // floats of weights per subnet

// Transposed weights: [o][field][i]  (field-major so lane=i loads coalesce)
__device__ float g_wt[(size_t)OUTSZ * NF * INSZ];

typedef unsigned long long u64;

__device__ __forceinline__ u64 pk(float a, float b) {
    u64 r; asm("mov.b64 %0, {%1, %2};" : "=l"(r) : "f"(a), "f"(b)); return r;
}
__device__ __forceinline__ void upk(u64 v, float& a, float& b) {
    asm("mov.b64 {%0, %1}, %2;" : "=f"(a), "=f"(b) : "l"(v));
}
__device__ __forceinline__ u64 ffma2(u64 a, u64 b, u64 c) {
    u64 d; asm("fma.rn.f32x2 %0, %1, %2, %3;" : "=l"(d) : "l"(a), "l"(b), "l"(c)); return d;
}
__device__ __forceinline__ u64 fmul2(u64 a, u64 b) {
    u64 d; asm("mul.rn.f32x2 %0, %1, %2;" : "=l"(d) : "l"(a), "l"(b)); return d;
}

// ---------------------------------------------------------------------------
// Prep v2: coalesced reads (consecutive fields of one subnet are contiguous),
// smem transpose (padded rows, conflict-free), coalesced writes over i.
// Two halves to stay under the 48KB static smem limit.
// ---------------------------------------------------------------------------
__global__ void prep_kernel(const float* __restrict__ W1, const float* __restrict__ b1,
                            const float* __restrict__ W2, const float* __restrict__ b2,
                            const float* __restrict__ W3, const float* __restrict__ b3) {
    __shared__ float st[49 * 132];           // 25.9 KB
    const int o   = blockIdx.x;
    const int tid = threadIdx.x;             // 256 threads
    float* dst = g_wt + (size_t)o * (NF * INSZ);

    // ---- half A: fields 0..47  (W1:0-7, b1:8-15, W2[e<32]:16-47) ----
    for (int idx = tid; idx < 128 * 8; idx += 256) {
        int i = idx >> 3, h = idx & 7;
        st[h * 132 + i] = W1[(size_t)(i * OUTSZ + o) * 8 + h];
    }
    for (int idx = tid; idx < 128 * 8; idx += 256) {
        int i = idx >> 3, h = idx & 7;
        st[(8 + h) * 132 + i] = b1[(size_t)(i * OUTSZ + o) * 8 + h];
    }
    for (int idx = tid; idx < 128 * 32; idx += 256) {
        int i = idx >> 5, e = idx & 31;
        st[(16 + e) * 132 + i] = W2[(size_t)(i * OUTSZ + o) * 64 + e];
    }
    __syncthreads();
    for (int idx = tid; idx < 48 * 128; idx += 256) {
        int f = idx >> 7, i = idx & 127;
        dst[f * INSZ + i] = st[f * 132 + i];
    }
    __syncthreads();

    // ---- half B: fields 48..96 (W2[e>=32]:48-79, b2:80-87, W3:88-95, b3:96) ----
    for (int idx = tid; idx < 128 * 32; idx += 256) {
        int i = idx >> 5, e2 = idx & 31;
        st[e2 * 132 + i] = W2[(size_t)(i * OUTSZ + o) * 64 + 32 + e2];
    }
    for (int idx = tid; idx < 128 * 8; idx += 256) {
        int i = idx >> 3, h = idx & 7;
        st[(32 + h) * 132 + i] = b2[(size_t)(i * OUTSZ + o) * 8 + h];
    }
    for (int idx = tid; idx < 128 * 8; idx += 256) {
        int i = idx >> 3, h = idx & 7;
        st[(40 + h) * 132 + i] = W3[(size_t)(i * OUTSZ + o) * 8 + h];
    }
    for (int idx = tid; idx < 128; idx += 256) {
        st[48 * 132 + idx] = b3[(size_t)idx * OUTSZ + o];
    }
    __syncthreads();
    for (int idx = tid; idx < 49 * 128; idx += 256) {
        int fl = idx >> 7, i = idx & 127;
        dst[(48 + fl) * INSZ + i] = st[fl * 132 + i];
    }
}

// ---------------------------------------------------------------------------
// Main: block = (o, batch-chunk of 64); thread = input feature i.
// f32x2-packed weights over hidden dim (loop-invariant registers).
// x loads software-pipelined 8 deep; reduction spread over all 128 threads.
// ---------------------------------------------------------------------------
__global__ void __launch_bounds__(128, 3)
mlpkan_main(const float* __restrict__ x, float* __restrict__ out) {
    const int o     = blockIdx.x;
    const int chunk = blockIdx.y;
    const int i     = threadIdx.x;

    __shared__ float red[32 * 129];   // [b_sub][i] padded: conflict-free R/W
    __shared__ float pr[4 * 33];      // partial sums [quarter][bb]

    // ---- load this thread's 97 weights (fully coalesced: lane = i) ----
    const float* wt = g_wt + (size_t)o * (NF * INSZ) + i;
    float w1[8], B1[8], w2[8][8], B2[8], w3[8], b3v;
#pragma unroll
    for (int h = 0; h < 8; h++) w1[h] = wt[h * INSZ];
#pragma unroll
    for (int h = 0; h < 8; h++) B1[h] = wt[(8 + h) * INSZ];
#pragma unroll
    for (int j = 0; j < 8; j++)
#pragma unroll
        for (int k = 0; k < 8; k++) w2[j][k] = wt[(16 + j * 8 + k) * INSZ];
#pragma unroll
    for (int j = 0; j < 8; j++) B2[j] = wt[(80 + j) * INSZ];
#pragma unroll
    for (int k = 0; k < 8; k++) w3[k] = wt[(88 + k) * INSZ];
    b3v = wt[96 * INSZ];

    // ---- pre-pack all loop-invariant f32x2 operands (hidden dim pairs) ----
    u64 w1p[4], b1p[4], w2p[4][8], b2p[4], w3p[4], b3p;
#pragma unroll
    for (int p = 0; p < 4; p++) {
        w1p[p] = pk(w1[2 * p], w1[2 * p + 1]);
        b1p[p] = pk(B1[2 * p], B1[2 * p + 1]);
        b2p[p] = pk(B2[2 * p], B2[2 * p + 1]);
        w3p[p] = pk(w3[2 * p], w3[2 * p + 1]);
#pragma unroll
        for (int k = 0; k < 8; k++)
            w2p[p][k] = pk(w2[2 * p][k], w2[2 * p + 1][k]);
    }
    b3p = pk(b3v, 0.0f);   // bias lands in the low half of chain 0

    const float* xp = x + (size_t)chunk * BC * INSZ + i;

    // ---- 8-deep rolling register prefetch of x ----
    float vbuf[8];
#pragma unroll
    for (int p = 0; p < 8; p++) vbuf[p] = xp[(size_t)p * INSZ];

#pragma unroll 1
    for (int sub = 0; sub < BC / 32; sub++) {
#pragma unroll 1
        for (int g = 0; g < 4; g++) {
#pragma unroll
            for (int u = 0; u < 8; u++) {
                const int b = sub * 32 + g * 8 + u;   // batch elem within chunk
                float v = vbuf[u];
                const int pb = b + 8;                  // prefetch 8 ahead
                if (pb < BC) vbuf[u] = xp[(size_t)pb * INSZ];

                u64 vp = pk(v, v);

                // layer 1: h1 = relu(w1*v + b1), produce splatted pairs s[k]
                u64 s[8];
#pragma unroll
                for (int p = 0; p < 4; p++) {
                    u64 t = ffma2(w1p[p], vp, b1p[p]);
                    float ta, tb; upk(t, ta, tb);
                    ta = fmaxf(ta, 0.0f);
                    tb = fmaxf(tb, 0.0f);
                    s[2 * p]     = pk(ta, ta);
                    s[2 * p + 1] = pk(tb, tb);
                }

                // layer 2: 4 packed output-pairs, 8-deep K accumulation each
                u64 h[4];
#pragma unroll
                for (int q = 0; q < 4; q++) {
                    u64 acc = ffma2(w2p[q][0], s[0], b2p[q]);
#pragma unroll
                    for (int k = 1; k < 8; k++) acc = ffma2(w2p[q][k], s[k], acc);
                    float ha, hb; upk(acc, ha, hb);
                    h[q] = pk(fmaxf(ha, 0.0f), fmaxf(hb, 0.0f));
                }

                // layer 3: two independent 2-deep chains
                u64 a0 = ffma2(w3p[0], h[0], b3p);
                u64 a1 = fmul2(w3p[1], h[1]);
                a0 = ffma2(w3p[2], h[2], a0);
                a1 = ffma2(w3p[3], h[3], a1);
                float x0, x1, y0, y1;
                upk(a0, x0, x1); upk(a1, y0, y1);

                red[(g * 8 + u) * 129 + i] = (x0 + x1) + (y0 + y1);
            }
        }
        __syncthreads();

        // spread reduction: thread t sums i-slice [32*(t>>5), +32) of bb = t&31
        {
            const int rb = i & 31, rq = i >> 5;
            const float* rr = &red[rb * 129 + rq * 32];
            float s0 = 0.f, s1 = 0.f, s2 = 0.f, s3 = 0.f;
#pragma unroll
            for (int c = 0; c < 32; c += 4) {
                s0 += rr[c + 0]; s1 += rr[c + 1];
                s2 += rr[c + 2]; s3 += rr[c + 3];
            }
            pr[rq * 33 + rb] = (s0 + s1) + (s2 + s3);
        }
        __syncthreads();

        // 4-way combine + store (one warp; overlapped with next sub's compute)
        if (i < 32) {
            float r = (pr[i] + pr[33 + i]) + (pr[66 + i] + pr[99 + i]);
            out[(size_t)(chunk * BC + sub * 32 + i) * OUTSZ + o] = r;
        }
    }
}

// ---------------------------------------------------------------------------
extern "C" void kernel_launch(void* const* d_in, const int* in_sizes, int n_in,
                              void* d_out, int out_size) {
    const float* x  = (const float*)d_in[0];
    const float* W1 = (const float*)d_in[1];
    const float* b1 = (const float*)d_in[2];
    const float* W2 = (const float*)d_in[3];
    const float* b2 = (const float*)d_in[4];
    const float* W3 = (const float*)d_in[5];
    const float* b3 = (const float*)d_in[6];
    float* out = (float*)d_out;

    prep_kernel<<<OUTSZ, 256>>>(W1, b1, W2, b2, W3, b3);
    mlpkan_main<<<dim3(OUTSZ, NCHUNK), INSZ>>>(x, out);
}

// round 4
// speedup vs baseline: 1.1508x; 1.1508x over previous
#include <cuda_runtime.h>

// Problem constants
#define INSZ   128
#define OUTSZ  128
#define BATCH  1024

#define NCHUNK 8
#define BC     (BATCH / NCHUNK)   // 128 batch elems per block
#define PAD    133                // smem row pitch (5 mod 32 -> conflict-free e-major writes)

typedef unsigned long long u64;

__device__ __forceinline__ u64 pk(float a, float b) {
    u64 r; asm("mov.b64 %0, {%1, %2};" : "=l"(r) : "f"(a), "f"(b)); return r;
}
__device__ __forceinline__ void upk(u64 v, float& a, float& b) {
    asm("mov.b64 {%0, %1}, %2;" : "=f"(a), "=f"(b) : "l"(v));
}
__device__ __forceinline__ u64 ffma2(u64 a, u64 b, u64 c) {
    u64 d; asm("fma.rn.f32x2 %0, %1, %2, %3;" : "=l"(d) : "l"(a), "l"(b), "l"(c)); return d;
}
__device__ __forceinline__ u64 fmul2(u64 a, u64 b) {
    u64 d; asm("mul.rn.f32x2 %0, %1, %2;" : "=l"(d) : "l"(a), "l"(b)); return d;
}
__device__ __forceinline__ u64 fadd2(u64 a, u64 b) {
    u64 d; asm("add.rn.f32x2 %0, %1, %2;" : "=l"(d) : "l"(a), "l"(b)); return d;
}

// ---------------------------------------------------------------------------
// Fused kernel: block = (o, batch-chunk of 128); thread = input feature i.
// Stages its own weights (original layout -> smem transpose -> registers),
// then runs the f32x2-packed 1-8-8-1 MLP per batch elem with an 8-deep
// rolling x prefetch and an all-thread spread reduction.
// ---------------------------------------------------------------------------
__global__ void __launch_bounds__(128, 3)
mlpkan_fused(const float* __restrict__ x,
             const float* __restrict__ W1, const float* __restrict__ b1,
             const float* __restrict__ W2, const float* __restrict__ b2,
             const float* __restrict__ W3, const float* __restrict__ b3,
             float* __restrict__ out) {
    const int o     = blockIdx.x;
    const int chunk = blockIdx.y;
    const int i     = threadIdx.x;

    __shared__ float sm[49 * PAD];          // 26.1 KB: staging, then red/pr alias
    float* red = sm;                        // [32][129] padded
    float* pr  = sm + 32 * 129;             // [4][33]

    // ---- start x prefetch first so DRAM latency overlaps weight staging ----
    const float* xp = x + (size_t)chunk * BC * INSZ + i;
    float vbuf[8];
#pragma unroll
    for (int p = 0; p < 8; p++) vbuf[p] = xp[(size_t)p * INSZ];

    // =========== Phase A staging: W1 (f0-7), b1 (f8-15), W2 e<32 (f16-47) ====
#pragma unroll
    for (int r = 0; r < 8; r++) {           // 8 x 128 elems
        int idx = r * 128 + i, ii = idx >> 3, h = idx & 7;
        sm[h * PAD + ii] = W1[(size_t)(ii * OUTSZ + o) * 8 + h];
    }
#pragma unroll
    for (int r = 0; r < 8; r++) {
        int idx = r * 128 + i, ii = idx >> 3, h = idx & 7;
        sm[(8 + h) * PAD + ii] = b1[(size_t)(ii * OUTSZ + o) * 8 + h];
    }
#pragma unroll
    for (int r = 0; r < 32; r++) {          // 32 x 128 elems
        int idx = r * 128 + i, ii = idx >> 5, e = idx & 31;
        sm[(16 + e) * PAD + ii] = W2[(size_t)(ii * OUTSZ + o) * 64 + e];
    }
    __syncthreads();

    float w1[8], B1[8], w2[8][8];
#pragma unroll
    for (int h = 0; h < 8; h++) w1[h] = sm[h * PAD + i];
#pragma unroll
    for (int h = 0; h < 8; h++) B1[h] = sm[(8 + h) * PAD + i];
#pragma unroll
    for (int e = 0; e < 32; e++) w2[e >> 3][e & 7] = sm[(16 + e) * PAD + i];
    __syncthreads();

    // ===== Phase B staging: W2 e>=32 (r0-31), b2 (r32-39), W3 (r40-47), b3 (r48)
#pragma unroll
    for (int r = 0; r < 32; r++) {
        int idx = r * 128 + i, ii = idx >> 5, e = idx & 31;
        sm[e * PAD + ii] = W2[(size_t)(ii * OUTSZ + o) * 64 + 32 + e];
    }
#pragma unroll
    for (int r = 0; r < 8; r++) {
        int idx = r * 128 + i, ii = idx >> 3, h = idx & 7;
        sm[(32 + h) * PAD + ii] = b2[(size_t)(ii * OUTSZ + o) * 8 + h];
    }
#pragma unroll
    for (int r = 0; r < 8; r++) {
        int idx = r * 128 + i, ii = idx >> 3, h = idx & 7;
        sm[(40 + h) * PAD + ii] = W3[(size_t)(ii * OUTSZ + o) * 8 + h];
    }
    sm[48 * PAD + i] = b3[(size_t)i * OUTSZ + o];
    __syncthreads();

    float B2[8], w3[8], b3v;
#pragma unroll
    for (int e = 0; e < 32; e++) w2[4 + (e >> 3)][e & 7] = sm[e * PAD + i];
#pragma unroll
    for (int h = 0; h < 8; h++) B2[h] = sm[(32 + h) * PAD + i];
#pragma unroll
    for (int h = 0; h < 8; h++) w3[h] = sm[(40 + h) * PAD + i];
    b3v = sm[48 * PAD + i];
    __syncthreads();                        // sm now reusable as red/pr

    // ---- pre-pack all loop-invariant f32x2 operands (hidden dim pairs) ----
    u64 w1p[4], b1p[4], w2p[4][8], b2p[4], w3p[4], b3p;
#pragma unroll
    for (int p = 0; p < 4; p++) {
        w1p[p] = pk(w1[2 * p], w1[2 * p + 1]);
        b1p[p] = pk(B1[2 * p], B1[2 * p + 1]);
        b2p[p] = pk(B2[2 * p], B2[2 * p + 1]);
        w3p[p] = pk(w3[2 * p], w3[2 * p + 1]);
#pragma unroll
        for (int k = 0; k < 8; k++)
            w2p[p][k] = pk(w2[2 * p][k], w2[2 * p + 1][k]);
    }
    b3p = pk(b3v, 0.0f);   // bias folds into the low half of chain 0

#pragma unroll 1
    for (int sub = 0; sub < BC / 32; sub++) {
#pragma unroll 1
        for (int g = 0; g < 4; g++) {
#pragma unroll
            for (int u = 0; u < 8; u++) {
                const int b = sub * 32 + g * 8 + u;   // batch elem within chunk
                float v = vbuf[u];
                const int pb = b + 8;                  // prefetch 8 ahead
                if (pb < BC) vbuf[u] = xp[(size_t)pb * INSZ];

                u64 vp = pk(v, v);

                // layer 1: h1 = relu(w1*v + b1) -> splatted pairs s[k]
                u64 s[8];
#pragma unroll
                for (int p = 0; p < 4; p++) {
                    u64 t = ffma2(w1p[p], vp, b1p[p]);
                    float ta, tb; upk(t, ta, tb);
                    ta = fmaxf(ta, 0.0f);
                    tb = fmaxf(tb, 0.0f);
                    s[2 * p]     = pk(ta, ta);
                    s[2 * p + 1] = pk(tb, tb);
                }

                // layer 2: 4 packed output-pairs, 2 chains of 4 + packed add
                u64 h[4];
#pragma unroll
                for (int q = 0; q < 4; q++) {
                    u64 a0 = ffma2(w2p[q][0], s[0], b2p[q]);
                    u64 a1 = fmul2(w2p[q][1], s[1]);
                    a0 = ffma2(w2p[q][2], s[2], a0);
                    a1 = ffma2(w2p[q][3], s[3], a1);
                    a0 = ffma2(w2p[q][4], s[4], a0);
                    a1 = ffma2(w2p[q][5], s[5], a1);
                    a0 = ffma2(w2p[q][6], s[6], a0);
                    a1 = ffma2(w2p[q][7], s[7], a1);
                    u64 t = fadd2(a0, a1);
                    float ha, hb; upk(t, ha, hb);
                    h[q] = pk(fmaxf(ha, 0.0f), fmaxf(hb, 0.0f));
                }

                // layer 3: two independent 2-deep chains
                u64 a0 = ffma2(w3p[0], h[0], b3p);
                u64 a1 = fmul2(w3p[1], h[1]);
                a0 = ffma2(w3p[2], h[2], a0);
                a1 = ffma2(w3p[3], h[3], a1);
                float x0, x1, y0, y1;
                upk(a0, x0, x1); upk(a1, y0, y1);

                red[(g * 8 + u) * 129 + i] = (x0 + x1) + (y0 + y1);
            }
        }
        __syncthreads();

        // spread reduction: thread t sums i-slice [32*(t>>5), +32) of bb = t&31
        {
            const int rb = i & 31, rq = i >> 5;
            const float* rr = &red[rb * 129 + rq * 32];
            float s0 = 0.f, s1 = 0.f, s2 = 0.f, s3 = 0.f;
#pragma unroll
            for (int c = 0; c < 32; c += 4) {
                s0 += rr[c + 0]; s1 += rr[c + 1];
                s2 += rr[c + 2]; s3 += rr[c + 3];
            }
            pr[rq * 33 + rb] = (s0 + s1) + (s2 + s3);
        }
        __syncthreads();

        // 4-way combine + store (one warp; overlapped with next sub's compute)
        if (i < 32) {
            float r = (pr[i] + pr[33 + i]) + (pr[66 + i] + pr[99 + i]);
            out[(size_t)(chunk * BC + sub * 32 + i) * OUTSZ + o] = r;
        }
    }
}

// ---------------------------------------------------------------------------
extern "C" void kernel_launch(void* const* d_in, const int* in_sizes, int n_in,
                              void* d_out, int out_size) {
    const float* x  = (const float*)d_in[0];
    const float* W1 = (const float*)d_in[1];
    const float* b1 = (const float*)d_in[2];
    const float* W2 = (const float*)d_in[3];
    const float* b2 = (const float*)d_in[4];
    const float* W3 = (const float*)d_in[5];
    const float* b3 = (const float*)d_in[6];
    float* out = (float*)d_out;

    mlpkan_fused<<<dim3(OUTSZ, NCHUNK), INSZ>>>(x, W1, b1, W2, b2, W3, b3, out);
}

// round 5
// speedup vs baseline: 1.1546x; 1.0033x over previous
#include <cuda_runtime.h>

// Problem constants
#define INSZ   128
#define OUTSZ  128
#define BATCH  1024

#define NCHUNK 8
#define BC     (BATCH / NCHUNK)   // 128 batch elems per block
#define PAD    133                // smem row pitch (conflict-free staging writes)

typedef unsigned long long u64;

__device__ __forceinline__ u64 pk(float a, float b) {
    u64 r; asm("mov.b64 %0, {%1, %2};" : "=l"(r) : "f"(a), "f"(b)); return r;
}
__device__ __forceinline__ void upk(u64 v, float& a, float& b) {
    asm("mov.b64 {%0, %1}, %2;" : "=f"(a), "=f"(b) : "l"(v));
}
__device__ __forceinline__ u64 ffma2(u64 a, u64 b, u64 c) {
    u64 d; asm("fma.rn.f32x2 %0, %1, %2, %3;" : "=l"(d) : "l"(a), "l"(b), "l"(c)); return d;
}
__device__ __forceinline__ u64 fmul2(u64 a, u64 b) {
    u64 d; asm("mul.rn.f32x2 %0, %1, %2;" : "=l"(d) : "l"(a), "l"(b)); return d;
}
__device__ __forceinline__ u64 fadd2(u64 a, u64 b) {
    u64 d; asm("add.rn.f32x2 %0, %1, %2;" : "=l"(d) : "l"(a), "l"(b)); return d;
}

// ---------------------------------------------------------------------------
// Fused kernel: block = (o, batch-chunk of 128); thread = input feature i.
// 4 CTAs/SM (regs forced <=128). Weights staged block-locally into registers,
// f32x2-packed over the hidden dim; 4-deep rolling x prefetch; spread reduction.
// ---------------------------------------------------------------------------
__global__ void __launch_bounds__(128, 4)
mlpkan_fused(const float* __restrict__ x,
             const float* __restrict__ W1, const float* __restrict__ b1,
             const float* __restrict__ W2, const float* __restrict__ b2,
             const float* __restrict__ W3, const float* __restrict__ b3,
             float* __restrict__ out) {
    const int o     = blockIdx.x;
    const int chunk = blockIdx.y;
    const int i     = threadIdx.x;

    __shared__ float sm[49 * PAD];          // 26.1 KB: staging, then red/pr alias
    float* red = sm;                        // [32][129] padded
    float* pr  = sm + 32 * 129;             // [4][33]

    // ---- start x prefetch first so memory latency overlaps weight staging ----
    const float* xp = x + (size_t)chunk * BC * INSZ + i;
    float vbuf[4];
#pragma unroll
    for (int p = 0; p < 4; p++) vbuf[p] = xp[(size_t)p * INSZ];

    // =========== Phase A staging: W1 (f0-7), b1 (f8-15), W2 e<32 (f16-47) ====
#pragma unroll
    for (int r = 0; r < 8; r++) {
        int idx = r * 128 + i, ii = idx >> 3, h = idx & 7;
        sm[h * PAD + ii] = W1[(size_t)(ii * OUTSZ + o) * 8 + h];
    }
#pragma unroll
    for (int r = 0; r < 8; r++) {
        int idx = r * 128 + i, ii = idx >> 3, h = idx & 7;
        sm[(8 + h) * PAD + ii] = b1[(size_t)(ii * OUTSZ + o) * 8 + h];
    }
#pragma unroll
    for (int r = 0; r < 32; r++) {
        int idx = r * 128 + i, ii = idx >> 5, e = idx & 31;
        sm[(16 + e) * PAD + ii] = W2[(size_t)(ii * OUTSZ + o) * 64 + e];
    }
    __syncthreads();

    u64 w1p[4], b1p[4], w2p[4][8];
#pragma unroll
    for (int p = 0; p < 4; p++) {
        w1p[p] = pk(sm[(2 * p) * PAD + i], sm[(2 * p + 1) * PAD + i]);
        b1p[p] = pk(sm[(8 + 2 * p) * PAD + i], sm[(9 + 2 * p) * PAD + i]);
    }
#pragma unroll
    for (int p = 0; p < 2; p++)
#pragma unroll
        for (int k = 0; k < 8; k++)
            w2p[p][k] = pk(sm[(16 + (2 * p) * 8 + k) * PAD + i],
                           sm[(16 + (2 * p + 1) * 8 + k) * PAD + i]);
    __syncthreads();

    // ===== Phase B staging: W2 e>=32 (r0-31), b2 (r32-39), W3 (r40-47), b3 (r48)
#pragma unroll
    for (int r = 0; r < 32; r++) {
        int idx = r * 128 + i, ii = idx >> 5, e = idx & 31;
        sm[e * PAD + ii] = W2[(size_t)(ii * OUTSZ + o) * 64 + 32 + e];
    }
#pragma unroll
    for (int r = 0; r < 8; r++) {
        int idx = r * 128 + i, ii = idx >> 3, h = idx & 7;
        sm[(32 + h) * PAD + ii] = b2[(size_t)(ii * OUTSZ + o) * 8 + h];
    }
#pragma unroll
    for (int r = 0; r < 8; r++) {
        int idx = r * 128 + i, ii = idx >> 3, h = idx & 7;
        sm[(40 + h) * PAD + ii] = W3[(size_t)(ii * OUTSZ + o) * 8 + h];
    }
    sm[48 * PAD + i] = b3[(size_t)i * OUTSZ + o];
    __syncthreads();

    u64 b2p[4], w3p[4], b3p;
#pragma unroll
    for (int p = 0; p < 2; p++)
#pragma unroll
        for (int k = 0; k < 8; k++)
            w2p[2 + p][k] = pk(sm[((2 * p) * 8 + k) * PAD + i],
                               sm[((2 * p + 1) * 8 + k) * PAD + i]);
#pragma unroll
    for (int p = 0; p < 4; p++) {
        b2p[p] = pk(sm[(32 + 2 * p) * PAD + i], sm[(33 + 2 * p) * PAD + i]);
        w3p[p] = pk(sm[(40 + 2 * p) * PAD + i], sm[(41 + 2 * p) * PAD + i]);
    }
    b3p = pk(sm[48 * PAD + i], 0.0f);       // bias folds into low half of chain 0
    __syncthreads();                        // sm now reusable as red/pr

#pragma unroll 1
    for (int sub = 0; sub < BC / 32; sub++) {
#pragma unroll 1
        for (int g = 0; g < 8; g++) {
#pragma unroll
            for (int u = 0; u < 4; u++) {
                const int b = sub * 32 + g * 4 + u;   // batch elem within chunk
                float v = vbuf[u];
                const int pb = b + 4;                  // prefetch 4 ahead
                if (pb < BC) vbuf[u] = xp[(size_t)pb * INSZ];

                u64 vp = pk(v, v);

                // layer 1: h1 = relu(w1*v + b1) -> splatted pairs s[k]
                u64 s[8];
#pragma unroll
                for (int p = 0; p < 4; p++) {
                    u64 t = ffma2(w1p[p], vp, b1p[p]);
                    float ta, tb; upk(t, ta, tb);
                    ta = fmaxf(ta, 0.0f);
                    tb = fmaxf(tb, 0.0f);
                    s[2 * p]     = pk(ta, ta);
                    s[2 * p + 1] = pk(tb, tb);
                }

                // layer 2: 4 packed output-pairs, single 8-deep chain each
                u64 h[4];
#pragma unroll
                for (int q = 0; q < 4; q++) {
                    u64 acc = ffma2(w2p[q][0], s[0], b2p[q]);
#pragma unroll
                    for (int k = 1; k < 8; k++) acc = ffma2(w2p[q][k], s[k], acc);
                    float ha, hb; upk(acc, ha, hb);
                    h[q] = pk(fmaxf(ha, 0.0f), fmaxf(hb, 0.0f));
                }

                // layer 3: two 2-deep chains + packed combine
                u64 a0 = ffma2(w3p[0], h[0], b3p);
                u64 a1 = fmul2(w3p[1], h[1]);
                a0 = ffma2(w3p[2], h[2], a0);
                a1 = ffma2(w3p[3], h[3], a1);
                u64 t = fadd2(a0, a1);
                float x0, x1; upk(t, x0, x1);

                red[(g * 4 + u) * 129 + i] = x0 + x1;
            }
        }
        __syncthreads();

        // spread reduction: thread t sums i-slice [32*(t>>5), +32) of bb = t&31
        {
            const int rb = i & 31, rq = i >> 5;
            const float* rr = &red[rb * 129 + rq * 32];
            float s0 = 0.f, s1 = 0.f, s2 = 0.f, s3 = 0.f;
#pragma unroll
            for (int c = 0; c < 32; c += 4) {
                s0 += rr[c + 0]; s1 += rr[c + 1];
                s2 += rr[c + 2]; s3 += rr[c + 3];
            }
            pr[rq * 33 + rb] = (s0 + s1) + (s2 + s3);
        }
        __syncthreads();

        // 4-way combine + store (one warp; overlapped with next sub's compute)
        if (i < 32) {
            float r = (pr[i] + pr[33 + i]) + (pr[66 + i] + pr[99 + i]);
            out[(size_t)(chunk * BC + sub * 32 + i) * OUTSZ + o] = r;
        }
    }
}

// ---------------------------------------------------------------------------
extern "C" void kernel_launch(void* const* d_in, const int* in_sizes, int n_in,
                              void* d_out, int out_size) {
    const float* x  = (const float*)d_in[0];
    const float* W1 = (const float*)d_in[1];
    const float* b1 = (const float*)d_in[2];
    const float* W2 = (const float*)d_in[3];
    const float* b2 = (const float*)d_in[4];
    const float* W3 = (const float*)d_in[5];
    const float* b3 = (const float*)d_in[6];
    float* out = (float*)d_out;

    mlpkan_fused<<<dim3(OUTSZ, NCHUNK), INSZ>>>(x, W1, b1, W2, b2, W3, b3, out);
}